// round 10
// baseline (speedup 1.0000x reference)
#include <cuda_runtime.h>
#include <cuda_bf16.h>
#include <math.h>

#define NTOK 4096
#define DDIM 1024
#define NEXP 8
#define CAP  1280
#define NASSIGN (2 * NTOK)          // 8192 (k-major: p = k*NTOK + n)
#define NSLOT (NEXP * CAP)          // 10240
#define ROWF  (NEXP * CAP)          // 10240 floats per token row

// Output layout (fp32, concatenated in reference return order)
#define W_OFF 0ULL
#define M_OFF 41943040ULL
#define B_OFF 83886080ULL
#define L_OFF 94371840ULL
#define WM_VEC4 20971520ULL         // (W+M) floats / 4

// Persistent-kernel role partition (grid = 592, all co-resident @ 4 blocks/SM)
#define GRID   592
#define NFILL  398
#define LOG0   398
#define NLOG   32
#define RANKB  430
#define GATH0  431
#define NGATH  160                  // 10240 slots / 64 per block
#define SCATB  591

// Scratch (device globals; zero-initialized at module load)
__device__ int   g_topi[NTOK * 2];
__device__ float g_topp[NTOK * 2];
__device__ int   g_sidx[NASSIGN];
__device__ float g_sw[NASSIGN];
__device__ int   g_slot[NSLOT];
__device__ int   g_done_logits;     // -> NLOG
__device__ int   g_flag_rank;       // -> 1
__device__ int   g_done_fill;      // -> NFILL
__device__ int   g_done_consume;    // -> NGATH + 1 ; reset by scatter block

__device__ __forceinline__ void spin_ge(int* ctr, int target) {
    if (threadIdx.x == 0) {
        while (atomicAdd(ctr, 0) < target) __nanosleep(128);
    }
    __syncthreads();
    __threadfence();
}
__device__ __forceinline__ void publish(int* ctr) {
    __syncthreads();
    if (threadIdx.x == 0) { __threadfence(); atomicAdd(ctr, 1); }
}

__global__ void __launch_bounds__(256, 4)
moe_persistent_kernel(const float* __restrict__ x,
                      const float* __restrict__ w,
                      float* __restrict__ out)
{
    const int b = blockIdx.x;
    const int t = threadIdx.x;

    if (b < NFILL) {
        // ------------------- zero-fill W + M (335.5 MB) -------------------
        float4* o = reinterpret_cast<float4*>(out);
        const float4 z = make_float4(0.f, 0.f, 0.f, 0.f);
        const size_t stride = (size_t)NFILL * 256;
        for (size_t c = (size_t)b * 256 + t; c < WM_VEC4; c += stride)
            __stcs(o + c, z);
        publish(&g_done_fill);
        return;
    }

    if (b < LOG0 + NLOG) {
        // ------------------- logits + top2 + softmax ----------------------
        __shared__ float4 sw4[NEXP * 256];       // 32 KB
        {
            const float4* w4 = reinterpret_cast<const float4*>(w);
            for (int i = t; i < NEXP * 256; i += 256) sw4[i] = w4[i];
        }
        __syncthreads();

        const int warp = t >> 5;
        const int lane = t & 31;
        const int nbase = (b - LOG0) * 128 + warp * 16;   // 16 tokens per warp

        for (int i0 = 0; i0 < 16; i0++) {
            const int n = nbase + i0;
            const float4* xr4 = reinterpret_cast<const float4*>(x + (size_t)n * DDIM);
            float acc[NEXP];
            #pragma unroll
            for (int e = 0; e < NEXP; e++) acc[e] = 0.f;
            #pragma unroll
            for (int i = 0; i < 8; i++) {
                const int d4 = i * 32 + lane;
                float4 xv = xr4[d4];
                #pragma unroll
                for (int e = 0; e < NEXP; e++) {
                    float4 wv = sw4[e * 256 + d4];
                    acc[e] = fmaf(xv.x, wv.x, acc[e]);
                    acc[e] = fmaf(xv.y, wv.y, acc[e]);
                    acc[e] = fmaf(xv.z, wv.z, acc[e]);
                    acc[e] = fmaf(xv.w, wv.w, acc[e]);
                }
            }
            #pragma unroll
            for (int off = 16; off > 0; off >>= 1) {
                #pragma unroll
                for (int e = 0; e < NEXP; e++)
                    acc[e] += __shfl_xor_sync(0xffffffffu, acc[e], off);
            }
            if (lane < NEXP)
                out[L_OFF + (size_t)n * NEXP + lane] = acc[lane];
            if (lane == 0) {
                int i0e = 0; float b0 = acc[0];
                #pragma unroll
                for (int e = 1; e < NEXP; e++)
                    if (acc[e] > b0) { b0 = acc[e]; i0e = e; }
                int i1e = -1; float b1 = -INFINITY;
                #pragma unroll
                for (int e = 0; e < NEXP; e++)
                    if (e != i0e && acc[e] > b1) { b1 = acc[e]; i1e = e; }
                float e1 = __expf(b1 - b0);
                float inv = 1.0f / (1.0f + e1);
                g_topi[n * 2 + 0] = i0e;
                g_topi[n * 2 + 1] = i1e;
                g_topp[n * 2 + 0] = inv;
                g_topp[n * 2 + 1] = e1 * inv;
            }
        }
        publish(&g_done_logits);
        return;
    }

    if (b == RANKB) {
        // --------- deterministic k-major rank, all 8 experts at once ------
        // packed 16-bit x4 counters in two uint64s; 256 threads x 32 pos.
        spin_ge(&g_done_logits, NLOG);

        for (int i = t; i < NSLOT; i += 256) g_slot[i] = -1;
        __syncthreads();

        const int lane = t & 31;
        const int wid = t >> 5;
        unsigned long long c0 = 0ull, c1 = 0ull;
        #pragma unroll
        for (int i = 0; i < 32; i++) {
            int p = t * 32 + i;
            int k = p >> 12;
            int n = p & (NTOK - 1);
            int e = g_topi[n * 2 + k];
            if (e < 4) c0 += 1ull << (e * 16);
            else       c1 += 1ull << ((e - 4) * 16);
        }
        unsigned long long s0 = c0, s1 = c1;
        #pragma unroll
        for (int off = 1; off < 32; off <<= 1) {
            unsigned long long v0 = __shfl_up_sync(0xffffffffu, s0, off);
            unsigned long long v1 = __shfl_up_sync(0xffffffffu, s1, off);
            if (lane >= off) { s0 += v0; s1 += v1; }
        }
        __shared__ unsigned long long ws0[8], ws1[8];
        if (lane == 31) { ws0[wid] = s0; ws1[wid] = s1; }
        __syncthreads();
        if (t == 0) {
            unsigned long long a0 = 0ull, a1 = 0ull;
            #pragma unroll
            for (int wj = 0; wj < 8; wj++) {
                unsigned long long t0 = ws0[wj], t1 = ws1[wj];
                ws0[wj] = a0; ws1[wj] = a1;
                a0 += t0; a1 += t1;
            }
        }
        __syncthreads();
        unsigned long long e0 = ws0[wid] + (s0 - c0);   // exclusive packed base
        unsigned long long e1 = ws1[wid] + (s1 - c1);

        int run[8];
        #pragma unroll
        for (int e = 0; e < 8; e++) run[e] = 0;
        #pragma unroll
        for (int i = 0; i < 32; i++) {
            int p = t * 32 + i;
            int k = p >> 12;
            int n = p & (NTOK - 1);
            int e = g_topi[n * 2 + k];
            int base = (e < 4) ? (int)((e0 >> (e * 16)) & 0xffff)
                               : (int)((e1 >> ((e - 4) * 16)) & 0xffff);
            int r = base + run[e];
            run[e]++;
            if (r < CAP) {
                g_sidx[p] = n * ROWF + e * CAP + r;
                g_sw[p]   = g_topp[n * 2 + k];
                g_slot[e * CAP + r] = n;
            } else {
                g_sidx[p] = -1;
            }
        }
        publish(&g_flag_rank);
        publish(&g_done_consume);
        return;
    }

    if (b < GATH0 + NGATH) {
        // ------------------- expert_batches gather ------------------------
        spin_ge(&g_flag_rank, 1);
        const int s0 = (b - GATH0) * 64;
        for (int i = 0; i < 64; i++) {
            int slot = s0 + i;
            int n = g_slot[slot];
            float4* dst = reinterpret_cast<float4*>(out + B_OFF + (size_t)slot * DDIM);
            if (n >= 0) {
                const float4* src = reinterpret_cast<const float4*>(x + (size_t)n * DDIM);
                __stcs(dst + t, src[t]);
            } else {
                __stcs(dst + t, make_float4(0.f, 0.f, 0.f, 0.f));
            }
        }
        publish(&g_done_consume);
        return;
    }

    // ---------------------- sparse W/M scatter + reset --------------------
    spin_ge(&g_flag_rank, 1);
    spin_ge(&g_done_fill, NFILL);
    for (int p = t; p < NASSIGN; p += 256) {
        int idx = g_sidx[p];
        if (idx >= 0) {
            out[W_OFF + (size_t)idx] = g_sw[p];
            out[M_OFF + (size_t)idx] = 1.0f;
        }
    }
    // reset sync state for the next graph replay (after all consumers done)
    spin_ge(&g_done_consume, NGATH + 1);
    __syncthreads();
    if (t == 0) {
        g_done_logits  = 0;
        g_flag_rank    = 0;
        g_done_fill    = 0;
        g_done_consume = 0;
        __threadfence();
    }
}

extern "C" void kernel_launch(void* const* d_in, const int* in_sizes, int n_in,
                              void* d_out, int out_size)
{
    const float* x = (const float*)d_in[0];       // [2,2048,1024]
    const float* w = (const float*)d_in[1];       // [8,1024]
    float* out = (float*)d_out;
    moe_persistent_kernel<<<GRID, 256>>>(x, w, out);
}

// round 11
// speedup vs baseline: 3.0777x; 3.0777x over previous
#include <cuda_runtime.h>
#include <cuda_bf16.h>
#include <math.h>

#define NTOK 4096
#define DDIM 1024
#define NEXP 8
#define CAP  1280
#define NASSIGN (2 * NTOK)          // 8192 (k-major: p = k*NTOK + n)
#define NSLOT (NEXP * CAP)          // 10240
#define ROWF  (NEXP * CAP)          // 10240 floats per token row

// Output layout (fp32, concatenated in reference return order)
#define W_OFF 0ULL
#define M_OFF 41943040ULL
#define B_OFF 83886080ULL
#define L_OFF 94371840ULL

// Fill chunking: W tokens [0,2048), W [2048,4096), M [0,2048), M [2048,4096)
#define HALF_FLOATS (2048ULL * ROWF)            // 20,971,520 floats per half-region

// Scratch (device globals; no allocations allowed)
__device__ int   g_topi[NTOK * 2];
__device__ float g_topp[NTOK * 2];
__device__ int   g_sidx[NASSIGN];   // flat idx into W region (or -1), p = k*NTOK+n
__device__ float g_sw[NASSIGN];     // weight for that entry
__device__ int   g_slot[NSLOT];

static cudaStream_t g_s1;
static cudaEvent_t  g_evFork, g_ev[4];
namespace {
struct StreamInit {
    StreamInit() {
        cudaStreamCreateWithFlags(&g_s1, cudaStreamNonBlocking);
        cudaEventCreateWithFlags(&g_evFork, cudaEventDisableTiming);
        for (int i = 0; i < 4; i++)
            cudaEventCreateWithFlags(&g_ev[i], cudaEventDisableTiming);
    }
} g_streamInit;
}

// ---------------------------------------------------------------------------
// 1) Fused router logits + top-2 + softmax. One warp per token, float4 I/O.
//    512 blocks (best measured configuration).
// ---------------------------------------------------------------------------
__global__ void logits_top2_kernel(const float* __restrict__ x,
                                   const float* __restrict__ w,
                                   float* __restrict__ out)
{
    __shared__ float4 sw4[NEXP * 256];          // 32 KB, [e][d4]
    {
        const float4* w4 = reinterpret_cast<const float4*>(w);
        for (int i = threadIdx.x; i < NEXP * 256; i += blockDim.x)
            sw4[i] = w4[i];
    }
    __syncthreads();

    const int warp = threadIdx.x >> 5;
    const int lane = threadIdx.x & 31;
    const int n = blockIdx.x * (blockDim.x >> 5) + warp;   // token
    if (n >= NTOK) return;

    const float4* xr4 = reinterpret_cast<const float4*>(x + (size_t)n * DDIM);
    float acc[NEXP];
    #pragma unroll
    for (int e = 0; e < NEXP; e++) acc[e] = 0.f;

    #pragma unroll
    for (int i = 0; i < 8; i++) {
        const int d4 = i * 32 + lane;
        float4 xv = xr4[d4];
        #pragma unroll
        for (int e = 0; e < NEXP; e++) {
            float4 wv = sw4[e * 256 + d4];
            acc[e] = fmaf(xv.x, wv.x, acc[e]);
            acc[e] = fmaf(xv.y, wv.y, acc[e]);
            acc[e] = fmaf(xv.z, wv.z, acc[e]);
            acc[e] = fmaf(xv.w, wv.w, acc[e]);
        }
    }
    #pragma unroll
    for (int off = 16; off > 0; off >>= 1) {
        #pragma unroll
        for (int e = 0; e < NEXP; e++)
            acc[e] += __shfl_xor_sync(0xffffffffu, acc[e], off);
    }
    if (lane < NEXP)
        out[L_OFF + (size_t)n * NEXP + lane] = acc[lane];

    if (lane == 0) {
        int i0 = 0; float b0 = acc[0];
        #pragma unroll
        for (int e = 1; e < NEXP; e++)
            if (acc[e] > b0) { b0 = acc[e]; i0 = e; }
        int i1 = -1; float b1 = -INFINITY;
        #pragma unroll
        for (int e = 0; e < NEXP; e++)
            if (e != i0 && acc[e] > b1) { b1 = acc[e]; i1 = e; }
        float e1 = __expf(b1 - b0);
        float inv = 1.0f / (1.0f + e1);
        g_topi[n * 2 + 0] = i0;
        g_topi[n * 2 + 1] = i1;
        g_topp[n * 2 + 0] = inv;
        g_topp[n * 2 + 1] = e1 * inv;
    }
}

// ---------------------------------------------------------------------------
// 2) Fused rank + slot map + packed scatter list. One block per expert;
//    deterministic k-major exclusive scan via shfl warp-scan (2 barriers).
// ---------------------------------------------------------------------------
__global__ void rank_slot_kernel()
{
    const int e = blockIdx.x;           // expert
    const int t = threadIdx.x;          // 1024 threads
    const int lane = t & 31;
    const int wid = t >> 5;             // 32 warps
    const int PER = NASSIGN / 1024;     // 8 positions per thread

    if (t < CAP) g_slot[e * CAP + t] = -1;
    if (t + 1024 < CAP) g_slot[e * CAP + t + 1024] = -1;

    int flag[8];
    int local[8];
    int cnt = 0;
    #pragma unroll
    for (int i = 0; i < PER; i++) {
        int p = t * PER + i;
        int k = p >> 12;
        int n = p & (NTOK - 1);
        int ex = g_topi[n * 2 + k];
        flag[i] = (ex == e);
        local[i] = cnt;
        cnt += flag[i];
    }

    int inc = cnt;
    #pragma unroll
    for (int off = 1; off < 32; off <<= 1) {
        int v = __shfl_up_sync(0xffffffffu, inc, off);
        if (lane >= off) inc += v;
    }
    __shared__ int swsum[32];
    if (lane == 31) swsum[wid] = inc;
    __syncthreads();
    if (wid == 0) {
        int v = swsum[lane];
        int iv = v;
        #pragma unroll
        for (int off = 1; off < 32; off <<= 1) {
            int u = __shfl_up_sync(0xffffffffu, iv, off);
            if (lane >= off) iv += u;
        }
        swsum[lane] = iv - v;           // exclusive warp offsets
    }
    __syncthreads();
    int excl = swsum[wid] + inc - cnt;

    #pragma unroll
    for (int i = 0; i < PER; i++) {
        if (flag[i]) {
            int p = t * PER + i;
            int k = p >> 12;
            int n = p & (NTOK - 1);
            int r = excl + local[i];
            if (r < CAP) {
                g_sidx[p] = n * ROWF + e * CAP + r;
                g_sw[p]   = g_topp[n * 2 + k];
                g_slot[e * CAP + r] = n;
            } else {
                g_sidx[p] = -1;
            }
        }
    }
}

// ---------------------------------------------------------------------------
// 3) expert_batches: slot (e,c) = verbatim x-row copy or zeros.
//    Streaming stores; x reads should hit L2 (warmed by the logits pass).
// ---------------------------------------------------------------------------
__global__ void gather_kernel(const float* __restrict__ x,
                              float* __restrict__ out)
{
    int slot = blockIdx.x;              // 0..NSLOT-1
    int n = g_slot[slot];
    float4* dst = reinterpret_cast<float4*>(out + B_OFF + (size_t)slot * DDIM);
    if (n >= 0) {
        const float4* src = reinterpret_cast<const float4*>(x + (size_t)n * DDIM);
        __stcs(dst + threadIdx.x, src[threadIdx.x]);
    } else {
        __stcs(dst + threadIdx.x, make_float4(0.f, 0.f, 0.f, 0.f));
    }
}

// ---------------------------------------------------------------------------
// 4) Sparse scatters per token-half: weights-only / mask-only.
//    4096 entries each: t -> k = t>>11, n = n0 + (t & 2047).
// ---------------------------------------------------------------------------
__global__ void scatter_w_kernel(float* __restrict__ out, int n0)
{
    int t = blockIdx.x * blockDim.x + threadIdx.x;
    if (t >= 2 * 2048) return;
    int p = (t >> 11) * NTOK + n0 + (t & 2047);
    int idx = g_sidx[p];
    if (idx >= 0) out[W_OFF + (size_t)idx] = g_sw[p];
}

__global__ void scatter_m_kernel(float* __restrict__ out, int n0)
{
    int t = blockIdx.x * blockDim.x + threadIdx.x;
    if (t >= 2 * 2048) return;
    int p = (t >> 11) * NTOK + n0 + (t & 2047);
    int idx = g_sidx[p];
    if (idx >= 0) out[M_OFF + (size_t)idx] = 1.0f;
}

extern "C" void kernel_launch(void* const* d_in, const int* in_sizes, int n_in,
                              void* d_out, int out_size)
{
    const float* x = (const float*)d_in[0];       // [2,2048,1024]
    const float* w = (const float*)d_in[1];       // [8,1024]
    float* out = (float*)d_out;

    // Fork: chunked driver memsets (driver-tuned store path) + per-chunk events.
    cudaEventRecord(g_evFork, 0);
    cudaStreamWaitEvent(g_s1, g_evFork, 0);
    cudaMemsetAsync(out + 0ULL * HALF_FLOATS, 0, HALF_FLOATS * 4, g_s1); // W [0,2048)
    cudaEventRecord(g_ev[0], g_s1);
    cudaMemsetAsync(out + 1ULL * HALF_FLOATS, 0, HALF_FLOATS * 4, g_s1); // W [2048,4096)
    cudaEventRecord(g_ev[1], g_s1);
    cudaMemsetAsync(out + 2ULL * HALF_FLOATS, 0, HALF_FLOATS * 4, g_s1); // M [0,2048)
    cudaEventRecord(g_ev[2], g_s1);
    cudaMemsetAsync(out + 3ULL * HALF_FLOATS, 0, HALF_FLOATS * 4, g_s1); // M [2048,4096)
    cudaEventRecord(g_ev[3], g_s1);

    // Main chain.
    logits_top2_kernel<<<512, 256>>>(x, w, out);
    rank_slot_kernel<<<NEXP, 1024>>>();
    gather_kernel<<<NSLOT, 256>>>(x, out);

    // Pipelined sparse scatters: each waits only on its own zeroed chunk.
    cudaStreamWaitEvent(0, g_ev[0], 0);
    scatter_w_kernel<<<16, 256>>>(out, 0);
    cudaStreamWaitEvent(0, g_ev[1], 0);
    scatter_w_kernel<<<16, 256>>>(out, 2048);
    cudaStreamWaitEvent(0, g_ev[2], 0);
    scatter_m_kernel<<<16, 256>>>(out, 0);
    cudaStreamWaitEvent(0, g_ev[3], 0);
    scatter_m_kernel<<<16, 256>>>(out, 2048);
}

// round 12
// speedup vs baseline: 3.4008x; 1.1050x over previous
#include <cuda_runtime.h>
#include <cuda_bf16.h>
#include <math.h>

#define NTOK 4096
#define DDIM 1024
#define NEXP 8
#define CAP  1280
#define NASSIGN (2 * NTOK)          // 8192 (k-major: p = k*NTOK + n)
#define NSLOT (NEXP * CAP)          // 10240
#define ROWF  (NEXP * CAP)          // 10240 floats per token row

// Output layout (fp32, concatenated in reference return order)
#define W_OFF 0ULL
#define M_OFF 41943040ULL
#define B_OFF 83886080ULL
#define L_OFF 94371840ULL

// Fill chunking: W tokens [0,2048), W [2048,4096), M [0,2048), M [2048,4096)
#define HALF_FLOATS (2048ULL * ROWF)            // 20,971,520 floats per half-region
#define HALF_VEC4   (HALF_FLOATS / 4)           // 5,242,880 float4

// Scratch (device globals; no allocations allowed)
__device__ int   g_topi[NTOK * 2];
__device__ float g_topp[NTOK * 2];
__device__ int   g_sidx[NASSIGN];   // flat idx into W region (or -1), p = k*NTOK+n
__device__ float g_sw[NASSIGN];     // weight for that entry
__device__ int   g_slot[NSLOT];

static cudaStream_t g_s1;           // HIGH PRIORITY: fill chain is the critical path
static cudaEvent_t  g_evFork, g_ev[4];
namespace {
struct StreamInit {
    StreamInit() {
        int lo = 0, hi = 0;
        cudaDeviceGetStreamPriorityRange(&lo, &hi);   // hi = numerically least
        cudaStreamCreateWithPriority(&g_s1, cudaStreamNonBlocking, hi);
        cudaEventCreateWithFlags(&g_evFork, cudaEventDisableTiming);
        for (int i = 0; i < 4; i++)
            cudaEventCreateWithFlags(&g_ev[i], cudaEventDisableTiming);
    }
} g_streamInit;
}

// ---------------------------------------------------------------------------
// 1) Fused router logits + top-2 + softmax. One warp per token, float4 I/O.
// ---------------------------------------------------------------------------
__global__ void logits_top2_kernel(const float* __restrict__ x,
                                   const float* __restrict__ w,
                                   float* __restrict__ out)
{
    __shared__ float4 sw4[NEXP * 256];          // 32 KB, [e][d4]
    {
        const float4* w4 = reinterpret_cast<const float4*>(w);
        for (int i = threadIdx.x; i < NEXP * 256; i += blockDim.x)
            sw4[i] = w4[i];
    }
    __syncthreads();

    const int warp = threadIdx.x >> 5;
    const int lane = threadIdx.x & 31;
    const int n = blockIdx.x * (blockDim.x >> 5) + warp;   // token
    if (n >= NTOK) return;

    const float4* xr4 = reinterpret_cast<const float4*>(x + (size_t)n * DDIM);
    float acc[NEXP];
    #pragma unroll
    for (int e = 0; e < NEXP; e++) acc[e] = 0.f;

    #pragma unroll
    for (int i = 0; i < 8; i++) {
        const int d4 = i * 32 + lane;
        float4 xv = xr4[d4];
        #pragma unroll
        for (int e = 0; e < NEXP; e++) {
            float4 wv = sw4[e * 256 + d4];
            acc[e] = fmaf(xv.x, wv.x, acc[e]);
            acc[e] = fmaf(xv.y, wv.y, acc[e]);
            acc[e] = fmaf(xv.z, wv.z, acc[e]);
            acc[e] = fmaf(xv.w, wv.w, acc[e]);
        }
    }
    #pragma unroll
    for (int off = 16; off > 0; off >>= 1) {
        #pragma unroll
        for (int e = 0; e < NEXP; e++)
            acc[e] += __shfl_xor_sync(0xffffffffu, acc[e], off);
    }
    if (lane < NEXP)
        out[L_OFF + (size_t)n * NEXP + lane] = acc[lane];

    if (lane == 0) {
        int i0 = 0; float b0 = acc[0];
        #pragma unroll
        for (int e = 1; e < NEXP; e++)
            if (acc[e] > b0) { b0 = acc[e]; i0 = e; }
        int i1 = -1; float b1 = -INFINITY;
        #pragma unroll
        for (int e = 0; e < NEXP; e++)
            if (e != i0 && acc[e] > b1) { b1 = acc[e]; i1 = e; }
        float e1 = __expf(b1 - b0);
        float inv = 1.0f / (1.0f + e1);
        g_topi[n * 2 + 0] = i0;
        g_topi[n * 2 + 1] = i1;
        g_topp[n * 2 + 0] = inv;
        g_topp[n * 2 + 1] = e1 * inv;
    }
}

// ---------------------------------------------------------------------------
// 2) Fused rank + slot map + packed scatter list. One block per expert;
//    deterministic k-major exclusive prefix scan (Hillis-Steele, as in the
//    77.9us baseline).
// ---------------------------------------------------------------------------
__global__ void rank_slot_kernel()
{
    const int e = blockIdx.x;           // expert
    const int t = threadIdx.x;          // 1024 threads
    const int PER = NASSIGN / 1024;     // 8 positions per thread

    if (t < CAP) g_slot[e * CAP + t] = -1;
    if (t + 1024 < CAP) g_slot[e * CAP + t + 1024] = -1;

    int flag[8];
    int local[8];
    int cnt = 0;
    #pragma unroll
    for (int i = 0; i < PER; i++) {
        int p = t * PER + i;
        int k = p >> 12;
        int n = p & (NTOK - 1);
        int ex = g_topi[n * 2 + k];
        flag[i] = (ex == e);
        local[i] = cnt;
        cnt += flag[i];
    }

    __shared__ int s[1024];
    s[t] = cnt;
    __syncthreads();
    #pragma unroll
    for (int off = 1; off < 1024; off <<= 1) {
        int vv = (t >= off) ? s[t - off] : 0;
        __syncthreads();
        s[t] += vv;
        __syncthreads();
    }
    int excl = s[t] - cnt;

    #pragma unroll
    for (int i = 0; i < PER; i++) {
        if (flag[i]) {
            int p = t * PER + i;
            int k = p >> 12;
            int n = p & (NTOK - 1);
            int r = excl + local[i];
            if (r < CAP) {
                g_sidx[p] = n * ROWF + e * CAP + r;
                g_sw[p]   = g_topp[n * 2 + k];
                g_slot[e * CAP + r] = n;
            } else {
                g_sidx[p] = -1;
            }
        }
    }
}

// ---------------------------------------------------------------------------
// 3) expert_batches: slot (e,c) = verbatim x-row copy or zeros.
// ---------------------------------------------------------------------------
__global__ void gather_kernel(const float* __restrict__ x,
                              float* __restrict__ out)
{
    int slot = blockIdx.x;              // 0..NSLOT-1
    int n = g_slot[slot];
    float4* dst = reinterpret_cast<float4*>(out + B_OFF + (size_t)slot * DDIM);
    if (n >= 0) {
        const float4* src = reinterpret_cast<const float4*>(x + (size_t)n * DDIM);
        __stcs(dst + threadIdx.x, src[threadIdx.x]);
    } else {
        __stcs(dst + threadIdx.x, make_float4(0.f, 0.f, 0.f, 0.f));
    }
}

// ---------------------------------------------------------------------------
// 4) Chunked zero-fill with evict-first streaming stores.
// ---------------------------------------------------------------------------
__global__ void fill_cs_kernel(float4* __restrict__ base)
{
    const float4 z = make_float4(0.f, 0.f, 0.f, 0.f);
    size_t stride = (size_t)gridDim.x * blockDim.x;
    for (size_t c = (size_t)blockIdx.x * blockDim.x + threadIdx.x;
         c < HALF_VEC4; c += stride)
        __stcs(base + c, z);
}

// ---------------------------------------------------------------------------
// 5) Sparse scatters: all weights at once; masks per token-half.
// ---------------------------------------------------------------------------
__global__ void scatter_w_all_kernel(float* __restrict__ out)
{
    int p = blockIdx.x * blockDim.x + threadIdx.x;
    if (p >= NASSIGN) return;
    int idx = g_sidx[p];
    if (idx >= 0) out[W_OFF + (size_t)idx] = g_sw[p];
}

__global__ void scatter_m_kernel(float* __restrict__ out, int n0)
{
    int t = blockIdx.x * blockDim.x + threadIdx.x;
    if (t >= 2 * 2048) return;
    int p = (t >> 11) * NTOK + n0 + (t & 2047);
    int idx = g_sidx[p];
    if (idx >= 0) out[M_OFF + (size_t)idx] = 1.0f;
}

extern "C" void kernel_launch(void* const* d_in, const int* in_sizes, int n_in,
                              void* d_out, int out_size)
{
    const float* x = (const float*)d_in[0];       // [2,2048,1024]
    const float* w = (const float*)d_in[1];       // [8,1024]
    float* out = (float*)d_out;
    float4* out4 = (float4*)d_out;

    // Fork: chunked zero-fill on HIGH-PRIORITY side stream (critical path).
    cudaEventRecord(g_evFork, 0);
    cudaStreamWaitEvent(g_s1, g_evFork, 0);
    fill_cs_kernel<<<4096, 256, 0, g_s1>>>(out4 + 0 * HALF_VEC4);   // W tokens [0,2048)
    cudaEventRecord(g_ev[0], g_s1);
    fill_cs_kernel<<<4096, 256, 0, g_s1>>>(out4 + 1 * HALF_VEC4);   // W tokens [2048,4096)
    cudaEventRecord(g_ev[1], g_s1);
    fill_cs_kernel<<<4096, 256, 0, g_s1>>>(out4 + 2 * HALF_VEC4);   // M tokens [0,2048)
    cudaEventRecord(g_ev[2], g_s1);
    fill_cs_kernel<<<4096, 256, 0, g_s1>>>(out4 + 3 * HALF_VEC4);   // M tokens [2048,4096)
    cudaEventRecord(g_ev[3], g_s1);

    // Main chain (low priority; has ~20us of slack vs the fill chain).
    logits_top2_kernel<<<512, 256>>>(x, w, out);
    rank_slot_kernel<<<NEXP, 1024>>>();
    gather_kernel<<<NSLOT, 256>>>(x, out);

    // Pipelined sparse scatters: each waits only on its own zeroed region.
    cudaStreamWaitEvent(0, g_ev[1], 0);
    scatter_w_all_kernel<<<32, 256>>>(out);       // whole W region zeroed
    cudaStreamWaitEvent(0, g_ev[2], 0);
    scatter_m_kernel<<<16, 256>>>(out, 0);
    cudaStreamWaitEvent(0, g_ev[3], 0);
    scatter_m_kernel<<<16, 256>>>(out, 2048);     // tiny tail (~2-3us)
}